// round 15
// baseline (speedup 1.0000x reference)
#include <cuda_runtime.h>
#include <math.h>
#include <stdint.h>

// ---------------- scratch (device globals; no allocation allowed) ----------
#define TLEN 4096
__device__ float g_q[TLEN * 2048];
__device__ float g_k[TLEN * 512];
__device__ float g_v[TLEN * 512];
__device__ float g_att[TLEN * 2048];
// tf32 pre-converted GEMM operands
__device__ uint32_t g_xt[TLEN * 2048];
__device__ uint32_t g_wt[3072 * 2048];   // [wq;wk;wv] tf32
__device__ uint32_t g_ot[2048 * 2048];   // wo tf32
__device__ uint32_t g_at[TLEN * 2048];   // att tf32

__device__ __forceinline__ uint32_t f2tf(float x) {
    uint32_t r;
    asm("cvt.rna.tf32.f32 %0, %1;" : "=r"(r) : "f"(x));
    return r;
}
__device__ __forceinline__ void mma_tf32(float c[4], const uint32_t a[4],
                                         const uint32_t b0, const uint32_t b1) {
    asm volatile(
        "mma.sync.aligned.m16n8k8.row.col.f32.tf32.tf32.f32 "
        "{%0,%1,%2,%3},{%4,%5,%6,%7},{%8,%9},{%0,%1,%2,%3};\n"
        : "+f"(c[0]), "+f"(c[1]), "+f"(c[2]), "+f"(c[3])
        : "r"(a[0]), "r"(a[1]), "r"(a[2]), "r"(a[3]), "r"(b0), "r"(b1));
}
__device__ __forceinline__ void cp16(uint32_t saddr, const void* gptr) {
    asm volatile("cp.async.ca.shared.global [%0], [%1], 16;\n"
                 :: "r"(saddr), "l"(gptr));
}
__device__ __forceinline__ void ldsm4(uint32_t r[4], uint32_t addr) {
    asm volatile("ldmatrix.sync.aligned.m8n8.x4.shared.b16 {%0,%1,%2,%3}, [%4];"
                 : "=r"(r[0]), "=r"(r[1]), "=r"(r[2]), "=r"(r[3]) : "r"(addr));
}

// ---------------- fp32 -> tf32 conversion ---------------------------------
__global__ __launch_bounds__(256) void conv_tf32(
    const float* __restrict__ src, uint32_t* __restrict__ dst, int n)
{
    int i = (blockIdx.x * 256 + threadIdx.x) * 4;
    if (i >= n) return;
    float4 x = *(const float4*)(src + i);
    *(uint4*)(dst + i) = make_uint4(f2tf(x.x), f2tf(x.y), f2tf(x.z), f2tf(x.w));
}

// ====== cp.async + ldmatrix TF32 GEMM: C[M,N] = A[M,K] * B[N,K]^T =========
// A, B pre-converted tf32. Tile 128x128x32, 256 thr, warp tile 64x32.
// 3 smem stages x (As[128][36] + Bs[128][36]); fragments via ldmatrix.x4.
#define GPAD 36
#define STGW 9216          // words per stage
#define GEMM_SMEM 110592   // 3 stages

__global__ __launch_bounds__(256, 2) void gemm_cp(
    const uint32_t* __restrict__ A, const uint32_t* __restrict__ B,
    float* __restrict__ c0, int nc0, int ld0,
    float* __restrict__ c1, int nc1, int ld1,
    float* __restrict__ c2, int ld2, int K)
{
    extern __shared__ uint32_t sm[];
    const uint32_t sbase = (uint32_t)__cvta_generic_to_shared(sm);

    const int tid  = threadIdx.x;
    const int warp = tid >> 5;
    const int lane = tid & 31;
    const int gid  = lane >> 2;
    const int tig  = lane & 3;
    const int wm   = (warp >> 2) * 64;
    const int wn   = (warp & 3) * 32;
    const int m0   = blockIdx.y * 128;
    const int n0   = blockIdx.x * 128;

    const int lr = tid >> 3;         // 0..31
    const int lk = (tid & 7) * 4;    // 0..28

    // ldmatrix per-lane source rows/cols
    const int aRow = wm + ((lane >> 3) & 1) * 8 + (lane & 7);
    const int aCol = (lane >> 4) * 4;
    const int bRow = wn + (lane >> 4) * 8 + (lane & 7);
    const int bCol = ((lane >> 3) & 1) * 4;
    const uint32_t aAddr0 = sbase + (aRow * GPAD + aCol) * 4;
    const uint32_t bAddr0 = sbase + (4608 + bRow * GPAD + bCol) * 4;

    float acc[4][4][4];
#pragma unroll
    for (int mi = 0; mi < 4; mi++)
#pragma unroll
        for (int ni = 0; ni < 4; ni++)
#pragma unroll
            for (int r = 0; r < 4; r++) acc[mi][ni][r] = 0.0f;

    const uint32_t* Ap = A + (size_t)(m0 + lr) * K + lk;
    const uint32_t* Bp = B + (size_t)(n0 + lr) * K + lk;
    const int NT = K >> 5;

    auto issue = [&](int kt) {
        const int buf = kt % 3;
        const uint32_t sa = sbase + (buf * STGW + lr * GPAD + lk) * 4;
        const uint32_t sb = sa + 4608 * 4;
        const uint32_t* ap = Ap + kt * 32;
        const uint32_t* bp = Bp + kt * 32;
#pragma unroll
        for (int i = 0; i < 4; i++) {
            cp16(sa + i * 32 * GPAD * 4, ap + (size_t)i * 32 * K);
            cp16(sb + i * 32 * GPAD * 4, bp + (size_t)i * 32 * K);
        }
    };

    issue(0);
    asm volatile("cp.async.commit_group;\n");
    if (NT > 1) issue(1);
    asm volatile("cp.async.commit_group;\n");

    for (int kt = 0; kt < NT; kt++) {
        asm volatile("cp.async.wait_group 1;\n");
        __syncthreads();

        if (kt + 2 < NT) issue(kt + 2);
        asm volatile("cp.async.commit_group;\n");

        const uint32_t stg = (kt % 3) * STGW * 4;
        const uint32_t aS = aAddr0 + stg;
        const uint32_t bS = bAddr0 + stg;

#pragma unroll
        for (int ks = 0; ks < 4; ks++) {
            const uint32_t ko = ks * 32;   // ks*8 words
            uint32_t af[4][4];
#pragma unroll
            for (int mi = 0; mi < 4; mi++)
                ldsm4(af[mi], aS + mi * 16 * GPAD * 4 + ko);
            uint32_t bf[2][4];
#pragma unroll
            for (int p = 0; p < 2; p++)
                ldsm4(bf[p], bS + p * 16 * GPAD * 4 + ko);
#pragma unroll
            for (int ni = 0; ni < 4; ni++) {
                const uint32_t b0 = bf[ni >> 1][(ni & 1) * 2];
                const uint32_t b1 = bf[ni >> 1][(ni & 1) * 2 + 1];
#pragma unroll
                for (int mi = 0; mi < 4; mi++)
                    mma_tf32(acc[mi][ni], af[mi], b0, b1);
            }
        }
    }

    // CTA-level output routing (region boundaries are 128-aligned)
    float* dst; int coff, ld;
    if (n0 < nc0)            { dst = c0; coff = n0;             ld = ld0; }
    else if (n0 < nc0 + nc1) { dst = c1; coff = n0 - nc0;       ld = ld1; }
    else                     { dst = c2; coff = n0 - nc0 - nc1; ld = ld2; }

#pragma unroll
    for (int mi = 0; mi < 4; mi++) {
        const int r0 = m0 + wm + mi * 16 + gid;
#pragma unroll
        for (int ni = 0; ni < 4; ni++) {
            const int c = coff + wn + ni * 8 + tig * 2;
            *(float2*)&dst[(size_t)r0 * ld + c] =
                make_float2(acc[mi][ni][0], acc[mi][ni][1]);
            *(float2*)&dst[(size_t)(r0 + 8) * ld + c] =
                make_float2(acc[mi][ni][2], acc[mi][ni][3]);
        }
    }
}

// ---------------- RoPE ----------------------------------------------------
__global__ __launch_bounds__(256) void rope_kernel(
    float* __restrict__ q, float* __restrict__ k)
{
    const int t = blockIdx.x;
    const int idx = blockIdx.y * 256 + threadIdx.x;
    const int head = idx >> 6;
    const int d = idx & 63;

    const float invf = exp2f((float)d * (-13.287712379549449f / 64.0f));
    float fr = (float)t * invf;
    float c = cosf(fr), s = sinf(fr);

    float* base;
    if (head < 16) base = q + ((size_t)t * 16 + head) * 128;
    else           base = k + ((size_t)t * 4 + (head - 16)) * 128;

    float x1 = base[d];
    float x2 = base[d + 64];
    base[d]      = x1 * c - x2 * s;
    base[d + 64] = x1 * s + x2 * c;
}

// =============== tensor-core flash attention (unchanged, R6) ==============
#define KSTR 132
#define PSTR 36

__global__ __launch_bounds__(256) void attn_mma(
    const float* __restrict__ q, const float* __restrict__ k,
    const float* __restrict__ v, float* __restrict__ out)
{
    __shared__ uint32_t KP[4608];
    __shared__ uint32_t Vs[32 * KSTR];

    const int t0   = blockIdx.x * 32;
    const int gh   = blockIdx.y;
    const int tid  = threadIdx.x;
    const int warp = tid >> 5;
    const int lane = tid & 31;
    const int g    = lane >> 2;
    const int tig  = lane & 3;
    const float scale = 0.08838834764831845f;

    const int mA = warp * 16 + g;
    const int mB = mA + 8;
    const int tA = t0 + (mA & 31), tB = t0 + (mB & 31);
    const int hA = gh * 4 + (mA >> 5), hB = gh * 4 + (mB >> 5);

    uint32_t qa[16][4];
    const float* qAp = q + ((size_t)tA * 16 + hA) * 128;
    const float* qBp = q + ((size_t)tB * 16 + hB) * 128;
#pragma unroll
    for (int ks = 0; ks < 16; ks++) {
        qa[ks][0] = f2tf(qAp[8 * ks + tig]);
        qa[ks][1] = f2tf(qBp[8 * ks + tig]);
        qa[ks][2] = f2tf(qAp[8 * ks + tig + 4]);
        qa[ks][3] = f2tf(qBp[8 * ks + tig + 4]);
    }

    float oa[16][4];
#pragma unroll
    for (int i = 0; i < 16; i++)
#pragma unroll
        for (int r = 0; r < 4; r++) oa[i][r] = 0.0f;
    float rmA = -1e30f, rmB = -1e30f, rlA = 0.0f, rlB = 0.0f;

    uint32_t* Pw = &KP[warp * 16 * PSTR];

    for (int c = 0; c < 17; c++) {
        const int sb = t0 - 512 + 32 * c;
        if (sb + 31 < 0) continue;

#pragma unroll
        for (int i = 0; i < 4; i++) {
            int idx = tid + 256 * i;
            int row = idx >> 5;
            int c4  = (idx & 31) * 4;
            int s = sb + row;
            float4 k4 = make_float4(0.f, 0.f, 0.f, 0.f);
            float4 v4 = make_float4(0.f, 0.f, 0.f, 0.f);
            if (s >= 0) {
                k4 = *(const float4*)&k[((size_t)s * 4 + gh) * 128 + c4];
                v4 = *(const float4*)&v[((size_t)s * 4 + gh) * 128 + c4];
            }
            uint4 kp = make_uint4(f2tf(k4.x), f2tf(k4.y), f2tf(k4.z), f2tf(k4.w));
            uint4 vp = make_uint4(f2tf(v4.x), f2tf(v4.y), f2tf(v4.z), f2tf(v4.w));
            *(uint4*)&KP[row * KSTR + c4] = kp;
            *(uint4*)&Vs[row * KSTR + c4] = vp;
        }
        __syncthreads();

        float sf[4][4];
#pragma unroll
        for (int ni = 0; ni < 4; ni++)
#pragma unroll
            for (int r = 0; r < 4; r++) sf[ni][r] = 0.0f;
#pragma unroll
        for (int ks = 0; ks < 16; ks++) {
            const int kk = ks * 8;
#pragma unroll
            for (int ni = 0; ni < 4; ni++) {
                uint32_t b0 = KP[(ni * 8 + g) * KSTR + kk + tig];
                uint32_t b1 = KP[(ni * 8 + g) * KSTR + kk + tig + 4];
                mma_tf32(sf[ni], qa[ks], b0, b1);
            }
        }
        __syncthreads();

        float cmA = -1e30f, cmB = -1e30f;
#pragma unroll
        for (int ni = 0; ni < 4; ni++) {
#pragma unroll
            for (int jj = 0; jj < 2; jj++) {
                const int s = sb + ni * 8 + tig * 2 + jj;
                bool okA = (s >= 0) && (s <= tA) && (tA - s <= 512);
                bool okB = (s >= 0) && (s <= tB) && (tB - s <= 512);
                sf[ni][jj]     = okA ? sf[ni][jj]     * scale : -1e30f;
                sf[ni][2 + jj] = okB ? sf[ni][2 + jj] * scale : -1e30f;
                cmA = fmaxf(cmA, sf[ni][jj]);
                cmB = fmaxf(cmB, sf[ni][2 + jj]);
            }
        }
        cmA = fmaxf(cmA, __shfl_xor_sync(0xffffffffu, cmA, 1));
        cmA = fmaxf(cmA, __shfl_xor_sync(0xffffffffu, cmA, 2));
        cmB = fmaxf(cmB, __shfl_xor_sync(0xffffffffu, cmB, 1));
        cmB = fmaxf(cmB, __shfl_xor_sync(0xffffffffu, cmB, 2));

        const float nmA = fmaxf(rmA, cmA), nmB = fmaxf(rmB, cmB);
        const float alA = __expf(rmA - nmA), alB = __expf(rmB - nmB);
        rmA = nmA; rmB = nmB;

        float clA = 0.f, clB = 0.f;
#pragma unroll
        for (int ni = 0; ni < 4; ni++) {
            float p0 = __expf(sf[ni][0] - nmA);
            float p1 = __expf(sf[ni][1] - nmA);
            float p2 = __expf(sf[ni][2] - nmB);
            float p3 = __expf(sf[ni][3] - nmB);
            clA += p0 + p1; clB += p2 + p3;
            const int col = ni * 8 + tig * 2;
            Pw[g * PSTR + col]           = f2tf(p0);
            Pw[g * PSTR + col + 1]       = f2tf(p1);
            Pw[(g + 8) * PSTR + col]     = f2tf(p2);
            Pw[(g + 8) * PSTR + col + 1] = f2tf(p3);
        }
        clA += __shfl_xor_sync(0xffffffffu, clA, 1);
        clA += __shfl_xor_sync(0xffffffffu, clA, 2);
        clB += __shfl_xor_sync(0xffffffffu, clB, 1);
        clB += __shfl_xor_sync(0xffffffffu, clB, 2);
        rlA = rlA * alA + clA;
        rlB = rlB * alB + clB;

#pragma unroll
        for (int ni2 = 0; ni2 < 16; ni2++) {
            oa[ni2][0] *= alA; oa[ni2][1] *= alA;
            oa[ni2][2] *= alB; oa[ni2][3] *= alB;
        }
        __syncwarp();

#pragma unroll
        for (int ks = 0; ks < 4; ks++) {
            const int kk = ks * 8;
            uint32_t pa[4];
            pa[0] = Pw[g * PSTR + kk + tig];
            pa[1] = Pw[(g + 8) * PSTR + kk + tig];
            pa[2] = Pw[g * PSTR + kk + tig + 4];
            pa[3] = Pw[(g + 8) * PSTR + kk + tig + 4];
#pragma unroll
            for (int ni2 = 0; ni2 < 16; ni2++) {
                uint32_t b0 = Vs[(kk + tig) * KSTR + ni2 * 8 + g];
                uint32_t b1 = Vs[(kk + tig + 4) * KSTR + ni2 * 8 + g];
                mma_tf32(oa[ni2], pa, b0, b1);
            }
        }
        __syncthreads();
    }

    const float ilA = 1.0f / rlA, ilB = 1.0f / rlB;
    float* oAp = out + ((size_t)tA * 16 + hA) * 128;
    float* oBp = out + ((size_t)tB * 16 + hB) * 128;
#pragma unroll
    for (int ni2 = 0; ni2 < 16; ni2++) {
        const int d0 = ni2 * 8 + tig * 2;
        *(float2*)&oAp[d0] = make_float2(oa[ni2][0] * ilA, oa[ni2][1] * ilA);
        *(float2*)&oBp[d0] = make_float2(oa[ni2][2] * ilB, oa[ni2][3] * ilB);
    }
}

// ---------------- launcher -------------------------------------------------
extern "C" void kernel_launch(void* const* d_in, const int* in_sizes, int n_in,
                              void* d_out, int out_size)
{
    const float* x  = (const float*)d_in[0];
    const float* wq = (const float*)d_in[1];
    const float* wk = (const float*)d_in[2];
    const float* wv = (const float*)d_in[3];
    const float* wo = (const float*)d_in[4];
    float* out = (float*)d_out;

    float *q, *k, *v, *att;
    uint32_t *xt, *wt, *ot, *at;
    cudaGetSymbolAddress((void**)&q,   g_q);
    cudaGetSymbolAddress((void**)&k,   g_k);
    cudaGetSymbolAddress((void**)&v,   g_v);
    cudaGetSymbolAddress((void**)&att, g_att);
    cudaGetSymbolAddress((void**)&xt,  g_xt);
    cudaGetSymbolAddress((void**)&wt,  g_wt);
    cudaGetSymbolAddress((void**)&ot,  g_ot);
    cudaGetSymbolAddress((void**)&at,  g_at);

    cudaFuncSetAttribute(gemm_cp, cudaFuncAttributeMaxDynamicSharedMemorySize,
                         GEMM_SMEM);

    // pre-convert all GEMM operands to tf32 (weights written concatenated)
    conv_tf32<<<8192, 256>>>(x,  xt, TLEN * 2048);
    conv_tf32<<<4096, 256>>>(wq, wt,              2048 * 2048);
    conv_tf32<<<1024, 256>>>(wk, wt + 2048 * 2048, 512 * 2048);
    conv_tf32<<<1024, 256>>>(wv, wt + 2560 * 2048, 512 * 2048);
    conv_tf32<<<4096, 256>>>(wo, ot, 2048 * 2048);

    // fused QKV projection
    gemm_cp<<<dim3(24, 32), 256, GEMM_SMEM>>>(xt, wt,
                                              q, 2048, 2048,
                                              k, 512, 512,
                                              v, 512, 2048);

    rope_kernel<<<dim3(TLEN, 5), 256>>>(q, k);

    attn_mma<<<dim3(TLEN / 32, 4), 256>>>(q, k, v, att);

    // output projection
    conv_tf32<<<8192, 256>>>(att, at, TLEN * 2048);
    gemm_cp<<<dim3(16, 32), 256, GEMM_SMEM>>>(at, ot,
                                              out, 2048, 2048,
                                              out, 0, 2048,
                                              out, 2048, 2048);
}

// round 16
// speedup vs baseline: 1.4867x; 1.4867x over previous
#include <cuda_runtime.h>
#include <math.h>
#include <stdint.h>

// ---------------- scratch (device globals; no allocation allowed) ----------
#define TLEN 4096
__device__ float g_q[TLEN * 2048];
__device__ float g_k[TLEN * 512];
__device__ float g_v[TLEN * 512];
__device__ float g_att[TLEN * 2048];
// tf32 pre-converted GEMM operands
__device__ uint32_t g_xt[TLEN * 2048];
__device__ uint32_t g_wt[3072 * 2048];   // [wq;wk;wv] tf32
__device__ uint32_t g_ot[2048 * 2048];   // wo tf32
__device__ uint32_t g_at[TLEN * 2048];   // att tf32

__device__ __forceinline__ uint32_t f2tf(float x) {
    uint32_t r;
    asm("cvt.rna.tf32.f32 %0, %1;" : "=r"(r) : "f"(x));
    return r;
}
__device__ __forceinline__ void mma_tf32(float c[4], const uint32_t a[4],
                                         const uint32_t b0, const uint32_t b1) {
    asm volatile(
        "mma.sync.aligned.m16n8k8.row.col.f32.tf32.tf32.f32 "
        "{%0,%1,%2,%3},{%4,%5,%6,%7},{%8,%9},{%0,%1,%2,%3};\n"
        : "+f"(c[0]), "+f"(c[1]), "+f"(c[2]), "+f"(c[3])
        : "r"(a[0]), "r"(a[1]), "r"(a[2]), "r"(a[3]), "r"(b0), "r"(b1));
}
__device__ __forceinline__ void cp16(uint32_t saddr, const void* gptr) {
    asm volatile("cp.async.ca.shared.global [%0], [%1], 16;\n"
                 :: "r"(saddr), "l"(gptr));
}

// ---------------- fp32 -> tf32 conversion ---------------------------------
__global__ __launch_bounds__(256) void conv_tf32(
    const float* __restrict__ src, uint32_t* __restrict__ dst, int n)
{
    int i = (blockIdx.x * 256 + threadIdx.x) * 4;
    if (i >= n) return;
    float4 x = *(const float4*)(src + i);
    *(uint4*)(dst + i) = make_uint4(f2tf(x.x), f2tf(x.y), f2tf(x.z), f2tf(x.w));
}

// ====== 64x64-warp TF32 GEMM: C[M,N] = A[M,K] * B[N,K]^T ==================
// A, B pre-converted tf32. CTA tile 128x128x32, 128 thr = 4 warps, warp
// tile 64x64 (4x8 m16n8k8, acc=128 regs). 2-stage cp.async double buffer.
// Rationale: smem crossbar is the GEMM bottleneck; square warp tiles
// minimize fragment bytes per MAC.
#define GPAD 36
#define STGW 9216          // words per stage (A 4608 + B 4608)
#define GEMM_SMEM 73728    // 2 stages

__global__ __launch_bounds__(128, 3) void gemm_w64(
    const uint32_t* __restrict__ A, const uint32_t* __restrict__ B,
    float* __restrict__ c0, int nc0, int ld0,
    float* __restrict__ c1, int nc1, int ld1,
    float* __restrict__ c2, int ld2, int K)
{
    extern __shared__ uint32_t sm[];
    const uint32_t sbase = (uint32_t)__cvta_generic_to_shared(sm);

    const int tid  = threadIdx.x;
    const int warp = tid >> 5;
    const int lane = tid & 31;
    const int gid  = lane >> 2;
    const int tig  = lane & 3;
    const int wm   = (warp >> 1) * 64;   // 2 warp-rows
    const int wn   = (warp & 1) * 64;    // 2 warp-cols
    const int m0   = blockIdx.y * 128;
    const int n0   = blockIdx.x * 128;

    const int lr = tid >> 3;         // 0..15
    const int lk = (tid & 7) * 4;    // 0..28

    float acc[4][8][4];
#pragma unroll
    for (int mi = 0; mi < 4; mi++)
#pragma unroll
        for (int ni = 0; ni < 8; ni++)
#pragma unroll
            for (int r = 0; r < 4; r++) acc[mi][ni][r] = 0.0f;

    const uint32_t* Ap = A + (size_t)(m0 + lr) * K + lk;
    const uint32_t* Bp = B + (size_t)(n0 + lr) * K + lk;
    const int NT = K >> 5;

    // one stage: 8 cp16 for A rows (16-row steps) + 8 for B
    auto issue = [&](int kt) {
        const uint32_t sa = sbase + ((kt & 1) * STGW + lr * GPAD + lk) * 4;
        const uint32_t sb = sa + 4608 * 4;
        const uint32_t* ap = Ap + kt * 32;
        const uint32_t* bp = Bp + kt * 32;
#pragma unroll
        for (int i = 0; i < 8; i++) {
            cp16(sa + i * 16 * GPAD * 4, ap + (size_t)i * 16 * K);
            cp16(sb + i * 16 * GPAD * 4, bp + (size_t)i * 16 * K);
        }
    };

    issue(0);
    asm volatile("cp.async.commit_group;\n");

    for (int kt = 0; kt < NT; kt++) {
        if (kt + 1 < NT) issue(kt + 1);
        asm volatile("cp.async.commit_group;\n");
        asm volatile("cp.async.wait_group 1;\n");
        __syncthreads();

        const uint32_t* As = sm + (kt & 1) * STGW;
        const uint32_t* Bs = As + 4608;

#pragma unroll
        for (int ks = 0; ks < 4; ks++) {
            const int kk = ks * 8;
            uint32_t af[4][4];
#pragma unroll
            for (int mi = 0; mi < 4; mi++) {
                const int r0 = wm + mi * 16 + gid;
                af[mi][0] = As[(r0    ) * GPAD + kk + tig];
                af[mi][1] = As[(r0 + 8) * GPAD + kk + tig];
                af[mi][2] = As[(r0    ) * GPAD + kk + tig + 4];
                af[mi][3] = As[(r0 + 8) * GPAD + kk + tig + 4];
            }
#pragma unroll
            for (int ni = 0; ni < 8; ni++) {
                const int c0i = wn + ni * 8 + gid;
                uint32_t b0 = Bs[c0i * GPAD + kk + tig];
                uint32_t b1 = Bs[c0i * GPAD + kk + tig + 4];
#pragma unroll
                for (int mi = 0; mi < 4; mi++)
                    mma_tf32(acc[mi][ni], af[mi], b0, b1);
            }
        }
        __syncthreads();   // all warps done with buf kt&1 before re-issue
    }

    // CTA-level output routing (region boundaries are 128-aligned)
    float* dst; int coff, ld;
    if (n0 < nc0)            { dst = c0; coff = n0;             ld = ld0; }
    else if (n0 < nc0 + nc1) { dst = c1; coff = n0 - nc0;       ld = ld1; }
    else                     { dst = c2; coff = n0 - nc0 - nc1; ld = ld2; }

#pragma unroll
    for (int mi = 0; mi < 4; mi++) {
        const int r0 = m0 + wm + mi * 16 + gid;
#pragma unroll
        for (int ni = 0; ni < 8; ni++) {
            const int c = coff + wn + ni * 8 + tig * 2;
            *(float2*)&dst[(size_t)r0 * ld + c] =
                make_float2(acc[mi][ni][0], acc[mi][ni][1]);
            *(float2*)&dst[(size_t)(r0 + 8) * ld + c] =
                make_float2(acc[mi][ni][2], acc[mi][ni][3]);
        }
    }
}

// ---------------- RoPE ----------------------------------------------------
__global__ __launch_bounds__(256) void rope_kernel(
    float* __restrict__ q, float* __restrict__ k)
{
    const int t = blockIdx.x;
    const int idx = blockIdx.y * 256 + threadIdx.x;
    const int head = idx >> 6;
    const int d = idx & 63;

    const float invf = exp2f((float)d * (-13.287712379549449f / 64.0f));
    float fr = (float)t * invf;
    float c = cosf(fr), s = sinf(fr);

    float* base;
    if (head < 16) base = q + ((size_t)t * 16 + head) * 128;
    else           base = k + ((size_t)t * 4 + (head - 16)) * 128;

    float x1 = base[d];
    float x2 = base[d + 64];
    base[d]      = x1 * c - x2 * s;
    base[d + 64] = x1 * s + x2 * c;
}

// =============== tensor-core flash attention (unchanged, R6) ==============
#define KSTR 132
#define PSTR 36

__global__ __launch_bounds__(256) void attn_mma(
    const float* __restrict__ q, const float* __restrict__ k,
    const float* __restrict__ v, float* __restrict__ out)
{
    __shared__ uint32_t KP[4608];
    __shared__ uint32_t Vs[32 * KSTR];

    const int t0   = blockIdx.x * 32;
    const int gh   = blockIdx.y;
    const int tid  = threadIdx.x;
    const int warp = tid >> 5;
    const int lane = tid & 31;
    const int g    = lane >> 2;
    const int tig  = lane & 3;
    const float scale = 0.08838834764831845f;

    const int mA = warp * 16 + g;
    const int mB = mA + 8;
    const int tA = t0 + (mA & 31), tB = t0 + (mB & 31);
    const int hA = gh * 4 + (mA >> 5), hB = gh * 4 + (mB >> 5);

    uint32_t qa[16][4];
    const float* qAp = q + ((size_t)tA * 16 + hA) * 128;
    const float* qBp = q + ((size_t)tB * 16 + hB) * 128;
#pragma unroll
    for (int ks = 0; ks < 16; ks++) {
        qa[ks][0] = f2tf(qAp[8 * ks + tig]);
        qa[ks][1] = f2tf(qBp[8 * ks + tig]);
        qa[ks][2] = f2tf(qAp[8 * ks + tig + 4]);
        qa[ks][3] = f2tf(qBp[8 * ks + tig + 4]);
    }

    float oa[16][4];
#pragma unroll
    for (int i = 0; i < 16; i++)
#pragma unroll
        for (int r = 0; r < 4; r++) oa[i][r] = 0.0f;
    float rmA = -1e30f, rmB = -1e30f, rlA = 0.0f, rlB = 0.0f;

    uint32_t* Pw = &KP[warp * 16 * PSTR];

    for (int c = 0; c < 17; c++) {
        const int sb = t0 - 512 + 32 * c;
        if (sb + 31 < 0) continue;

#pragma unroll
        for (int i = 0; i < 4; i++) {
            int idx = tid + 256 * i;
            int row = idx >> 5;
            int c4  = (idx & 31) * 4;
            int s = sb + row;
            float4 k4 = make_float4(0.f, 0.f, 0.f, 0.f);
            float4 v4 = make_float4(0.f, 0.f, 0.f, 0.f);
            if (s >= 0) {
                k4 = *(const float4*)&k[((size_t)s * 4 + gh) * 128 + c4];
                v4 = *(const float4*)&v[((size_t)s * 4 + gh) * 128 + c4];
            }
            uint4 kp = make_uint4(f2tf(k4.x), f2tf(k4.y), f2tf(k4.z), f2tf(k4.w));
            uint4 vp = make_uint4(f2tf(v4.x), f2tf(v4.y), f2tf(v4.z), f2tf(v4.w));
            *(uint4*)&KP[row * KSTR + c4] = kp;
            *(uint4*)&Vs[row * KSTR + c4] = vp;
        }
        __syncthreads();

        float sf[4][4];
#pragma unroll
        for (int ni = 0; ni < 4; ni++)
#pragma unroll
            for (int r = 0; r < 4; r++) sf[ni][r] = 0.0f;
#pragma unroll
        for (int ks = 0; ks < 16; ks++) {
            const int kk = ks * 8;
#pragma unroll
            for (int ni = 0; ni < 4; ni++) {
                uint32_t b0 = KP[(ni * 8 + g) * KSTR + kk + tig];
                uint32_t b1 = KP[(ni * 8 + g) * KSTR + kk + tig + 4];
                mma_tf32(sf[ni], qa[ks], b0, b1);
            }
        }
        __syncthreads();

        float cmA = -1e30f, cmB = -1e30f;
#pragma unroll
        for (int ni = 0; ni < 4; ni++) {
#pragma unroll
            for (int jj = 0; jj < 2; jj++) {
                const int s = sb + ni * 8 + tig * 2 + jj;
                bool okA = (s >= 0) && (s <= tA) && (tA - s <= 512);
                bool okB = (s >= 0) && (s <= tB) && (tB - s <= 512);
                sf[ni][jj]     = okA ? sf[ni][jj]     * scale : -1e30f;
                sf[ni][2 + jj] = okB ? sf[ni][2 + jj] * scale : -1e30f;
                cmA = fmaxf(cmA, sf[ni][jj]);
                cmB = fmaxf(cmB, sf[ni][2 + jj]);
            }
        }
        cmA = fmaxf(cmA, __shfl_xor_sync(0xffffffffu, cmA, 1));
        cmA = fmaxf(cmA, __shfl_xor_sync(0xffffffffu, cmA, 2));
        cmB = fmaxf(cmB, __shfl_xor_sync(0xffffffffu, cmB, 1));
        cmB = fmaxf(cmB, __shfl_xor_sync(0xffffffffu, cmB, 2));

        const float nmA = fmaxf(rmA, cmA), nmB = fmaxf(rmB, cmB);
        const float alA = __expf(rmA - nmA), alB = __expf(rmB - nmB);
        rmA = nmA; rmB = nmB;

        float clA = 0.f, clB = 0.f;
#pragma unroll
        for (int ni = 0; ni < 4; ni++) {
            float p0 = __expf(sf[ni][0] - nmA);
            float p1 = __expf(sf[ni][1] - nmA);
            float p2 = __expf(sf[ni][2] - nmB);
            float p3 = __expf(sf[ni][3] - nmB);
            clA += p0 + p1; clB += p2 + p3;
            const int col = ni * 8 + tig * 2;
            Pw[g * PSTR + col]           = f2tf(p0);
            Pw[g * PSTR + col + 1]       = f2tf(p1);
            Pw[(g + 8) * PSTR + col]     = f2tf(p2);
            Pw[(g + 8) * PSTR + col + 1] = f2tf(p3);
        }
        clA += __shfl_xor_sync(0xffffffffu, clA, 1);
        clA += __shfl_xor_sync(0xffffffffu, clA, 2);
        clB += __shfl_xor_sync(0xffffffffu, clB, 1);
        clB += __shfl_xor_sync(0xffffffffu, clB, 2);
        rlA = rlA * alA + clA;
        rlB = rlB * alB + clB;

#pragma unroll
        for (int ni2 = 0; ni2 < 16; ni2++) {
            oa[ni2][0] *= alA; oa[ni2][1] *= alA;
            oa[ni2][2] *= alB; oa[ni2][3] *= alB;
        }
        __syncwarp();

#pragma unroll
        for (int ks = 0; ks < 4; ks++) {
            const int kk = ks * 8;
            uint32_t pa[4];
            pa[0] = Pw[g * PSTR + kk + tig];
            pa[1] = Pw[(g + 8) * PSTR + kk + tig];
            pa[2] = Pw[g * PSTR + kk + tig + 4];
            pa[3] = Pw[(g + 8) * PSTR + kk + tig + 4];
#pragma unroll
            for (int ni2 = 0; ni2 < 16; ni2++) {
                uint32_t b0 = Vs[(kk + tig) * KSTR + ni2 * 8 + g];
                uint32_t b1 = Vs[(kk + tig + 4) * KSTR + ni2 * 8 + g];
                mma_tf32(oa[ni2], pa, b0, b1);
            }
        }
        __syncthreads();
    }

    const float ilA = 1.0f / rlA, ilB = 1.0f / rlB;
    float* oAp = out + ((size_t)tA * 16 + hA) * 128;
    float* oBp = out + ((size_t)tB * 16 + hB) * 128;
#pragma unroll
    for (int ni2 = 0; ni2 < 16; ni2++) {
        const int d0 = ni2 * 8 + tig * 2;
        *(float2*)&oAp[d0] = make_float2(oa[ni2][0] * ilA, oa[ni2][1] * ilA);
        *(float2*)&oBp[d0] = make_float2(oa[ni2][2] * ilB, oa[ni2][3] * ilB);
    }
}

// ---------------- launcher -------------------------------------------------
extern "C" void kernel_launch(void* const* d_in, const int* in_sizes, int n_in,
                              void* d_out, int out_size)
{
    const float* x  = (const float*)d_in[0];
    const float* wq = (const float*)d_in[1];
    const float* wk = (const float*)d_in[2];
    const float* wv = (const float*)d_in[3];
    const float* wo = (const float*)d_in[4];
    float* out = (float*)d_out;

    float *q, *k, *v, *att;
    uint32_t *xt, *wt, *ot, *at;
    cudaGetSymbolAddress((void**)&q,   g_q);
    cudaGetSymbolAddress((void**)&k,   g_k);
    cudaGetSymbolAddress((void**)&v,   g_v);
    cudaGetSymbolAddress((void**)&att, g_att);
    cudaGetSymbolAddress((void**)&xt,  g_xt);
    cudaGetSymbolAddress((void**)&wt,  g_wt);
    cudaGetSymbolAddress((void**)&ot,  g_ot);
    cudaGetSymbolAddress((void**)&at,  g_at);

    cudaFuncSetAttribute(gemm_w64, cudaFuncAttributeMaxDynamicSharedMemorySize,
                         GEMM_SMEM);

    // pre-convert all GEMM operands to tf32 (weights written concatenated)
    conv_tf32<<<8192, 256>>>(x,  xt, TLEN * 2048);
    conv_tf32<<<4096, 256>>>(wq, wt,              2048 * 2048);
    conv_tf32<<<1024, 256>>>(wk, wt + 2048 * 2048, 512 * 2048);
    conv_tf32<<<1024, 256>>>(wv, wt + 2560 * 2048, 512 * 2048);
    conv_tf32<<<4096, 256>>>(wo, ot, 2048 * 2048);

    // fused QKV projection
    gemm_w64<<<dim3(24, 32), 128, GEMM_SMEM>>>(xt, wt,
                                               q, 2048, 2048,
                                               k, 512, 512,
                                               v, 512, 2048);

    rope_kernel<<<dim3(TLEN, 5), 256>>>(q, k);

    attn_mma<<<dim3(TLEN / 32, 4), 256>>>(q, k, v, att);

    // output projection
    conv_tf32<<<8192, 256>>>(att, at, TLEN * 2048);
    gemm_w64<<<dim3(16, 32), 128, GEMM_SMEM>>>(at, ot,
                                               out, 2048, 2048,
                                               out, 0, 2048,
                                               out, 2048, 2048);
}

// round 17
// speedup vs baseline: 1.5052x; 1.0124x over previous
#include <cuda_runtime.h>
#include <math.h>
#include <stdint.h>

// ---------------- scratch (device globals; no allocation allowed) ----------
#define TLEN 4096
__device__ float g_q[TLEN * 2048];
__device__ float g_k[TLEN * 512];
__device__ float g_v[TLEN * 512];
__device__ float g_att[TLEN * 2048];
// tf32 pre-converted GEMM operands
__device__ uint32_t g_xt[TLEN * 2048];
__device__ uint32_t g_wt[3072 * 2048];   // [wq;wk;wv] tf32
__device__ uint32_t g_ot[2048 * 2048];   // wo tf32
__device__ uint32_t g_at[TLEN * 2048];   // att tf32

__device__ __forceinline__ uint32_t f2tf(float x) {
    uint32_t r;
    asm("cvt.rna.tf32.f32 %0, %1;" : "=r"(r) : "f"(x));
    return r;
}
__device__ __forceinline__ void mma_tf32(float c[4], const uint32_t a[4],
                                         const uint32_t b0, const uint32_t b1) {
    asm volatile(
        "mma.sync.aligned.m16n8k8.row.col.f32.tf32.tf32.f32 "
        "{%0,%1,%2,%3},{%4,%5,%6,%7},{%8,%9},{%0,%1,%2,%3};\n"
        : "+f"(c[0]), "+f"(c[1]), "+f"(c[2]), "+f"(c[3])
        : "r"(a[0]), "r"(a[1]), "r"(a[2]), "r"(a[3]), "r"(b0), "r"(b1));
}
__device__ __forceinline__ void cp16(uint32_t saddr, const void* gptr) {
    asm volatile("cp.async.ca.shared.global [%0], [%1], 16;\n"
                 :: "r"(saddr), "l"(gptr));
}

// ---------------- fp32 -> tf32 conversion ---------------------------------
__global__ __launch_bounds__(256) void conv_tf32(
    const float* __restrict__ src, uint32_t* __restrict__ dst, int n)
{
    int i = (blockIdx.x * 256 + threadIdx.x) * 4;
    if (i >= n) return;
    float4 x = *(const float4*)(src + i);
    *(uint4*)(dst + i) = make_uint4(f2tf(x.x), f2tf(x.y), f2tf(x.z), f2tf(x.w));
}

// ====== 64x64-warp TF32 GEMM, single barrier per K-tile ===================
// A, B pre-converted tf32. CTA tile 128x128x32, 128 thr = 4 warps, warp
// tile 64x64. 2-stage cp.async; cp issue moved AFTER the top sync so the
// trailing barrier is unnecessary (buf[(kt+1)&1]'s readers ran at kt-1 and
// have passed this iteration's sync). One __syncthreads per K-tile.
#define GPAD 36
#define STGW 9216          // words per stage (A 4608 + B 4608)
#define GEMM_SMEM 73728    // 2 stages

__global__ __launch_bounds__(128, 3) void gemm_w64(
    const uint32_t* __restrict__ A, const uint32_t* __restrict__ B,
    float* __restrict__ c0, int nc0, int ld0,
    float* __restrict__ c1, int nc1, int ld1,
    float* __restrict__ c2, int ld2, int K)
{
    extern __shared__ uint32_t sm[];
    const uint32_t sbase = (uint32_t)__cvta_generic_to_shared(sm);

    const int tid  = threadIdx.x;
    const int warp = tid >> 5;
    const int lane = tid & 31;
    const int gid  = lane >> 2;
    const int tig  = lane & 3;
    const int wm   = (warp >> 1) * 64;
    const int wn   = (warp & 1) * 64;
    const int m0   = blockIdx.y * 128;
    const int n0   = blockIdx.x * 128;

    const int lr = tid >> 3;         // 0..15
    const int lk = (tid & 7) * 4;    // 0..28

    float acc[4][8][4];
#pragma unroll
    for (int mi = 0; mi < 4; mi++)
#pragma unroll
        for (int ni = 0; ni < 8; ni++)
#pragma unroll
            for (int r = 0; r < 4; r++) acc[mi][ni][r] = 0.0f;

    const uint32_t* Ap = A + (size_t)(m0 + lr) * K + lk;
    const uint32_t* Bp = B + (size_t)(n0 + lr) * K + lk;
    const int NT = K >> 5;

    auto issue = [&](int kt) {
        const uint32_t sa = sbase + ((kt & 1) * STGW + lr * GPAD + lk) * 4;
        const uint32_t sb = sa + 4608 * 4;
        const uint32_t* ap = Ap + kt * 32;
        const uint32_t* bp = Bp + kt * 32;
#pragma unroll
        for (int i = 0; i < 8; i++) {
            cp16(sa + i * 16 * GPAD * 4, ap + (size_t)i * 16 * K);
            cp16(sb + i * 16 * GPAD * 4, bp + (size_t)i * 16 * K);
        }
    };

    issue(0);
    asm volatile("cp.async.commit_group;\n");

    for (int kt = 0; kt < NT; kt++) {
        asm volatile("cp.async.wait_group 0;\n");   // cp(kt) landed
        __syncthreads();                            // also: all done w/ other buf

        if (kt + 1 < NT) {
            issue(kt + 1);                          // safe: readers passed sync
            asm volatile("cp.async.commit_group;\n");
        }

        const uint32_t* As = sm + (kt & 1) * STGW;
        const uint32_t* Bs = As + 4608;

#pragma unroll
        for (int ks = 0; ks < 4; ks++) {
            const int kk = ks * 8;
            uint32_t af[4][4];
#pragma unroll
            for (int mi = 0; mi < 4; mi++) {
                const int r0 = wm + mi * 16 + gid;
                af[mi][0] = As[(r0    ) * GPAD + kk + tig];
                af[mi][1] = As[(r0 + 8) * GPAD + kk + tig];
                af[mi][2] = As[(r0    ) * GPAD + kk + tig + 4];
                af[mi][3] = As[(r0 + 8) * GPAD + kk + tig + 4];
            }
#pragma unroll
            for (int ni = 0; ni < 8; ni++) {
                const int c0i = wn + ni * 8 + gid;
                uint32_t b0 = Bs[c0i * GPAD + kk + tig];
                uint32_t b1 = Bs[c0i * GPAD + kk + tig + 4];
#pragma unroll
                for (int mi = 0; mi < 4; mi++)
                    mma_tf32(acc[mi][ni], af[mi], b0, b1);
            }
        }
    }

    // CTA-level output routing (region boundaries are 128-aligned)
    float* dst; int coff, ld;
    if (n0 < nc0)            { dst = c0; coff = n0;             ld = ld0; }
    else if (n0 < nc0 + nc1) { dst = c1; coff = n0 - nc0;       ld = ld1; }
    else                     { dst = c2; coff = n0 - nc0 - nc1; ld = ld2; }

#pragma unroll
    for (int mi = 0; mi < 4; mi++) {
        const int r0 = m0 + wm + mi * 16 + gid;
#pragma unroll
        for (int ni = 0; ni < 8; ni++) {
            const int c = coff + wn + ni * 8 + tig * 2;
            *(float2*)&dst[(size_t)r0 * ld + c] =
                make_float2(acc[mi][ni][0], acc[mi][ni][1]);
            *(float2*)&dst[(size_t)(r0 + 8) * ld + c] =
                make_float2(acc[mi][ni][2], acc[mi][ni][3]);
        }
    }
}

// ---------------- RoPE ----------------------------------------------------
__global__ __launch_bounds__(256) void rope_kernel(
    float* __restrict__ q, float* __restrict__ k)
{
    const int t = blockIdx.x;
    const int idx = blockIdx.y * 256 + threadIdx.x;
    const int head = idx >> 6;
    const int d = idx & 63;

    const float invf = exp2f((float)d * (-13.287712379549449f / 64.0f));
    float fr = (float)t * invf;
    float c = cosf(fr), s = sinf(fr);

    float* base;
    if (head < 16) base = q + ((size_t)t * 16 + head) * 128;
    else           base = k + ((size_t)t * 4 + (head - 16)) * 128;

    float x1 = base[d];
    float x2 = base[d + 64];
    base[d]      = x1 * c - x2 * s;
    base[d + 64] = x1 * s + x2 * c;
}

// =============== tensor-core flash attention (unchanged, R6) ==============
#define KSTR 132
#define PSTR 36

__global__ __launch_bounds__(256) void attn_mma(
    const float* __restrict__ q, const float* __restrict__ k,
    const float* __restrict__ v, float* __restrict__ out)
{
    __shared__ uint32_t KP[4608];
    __shared__ uint32_t Vs[32 * KSTR];

    const int t0   = blockIdx.x * 32;
    const int gh   = blockIdx.y;
    const int tid  = threadIdx.x;
    const int warp = tid >> 5;
    const int lane = tid & 31;
    const int g    = lane >> 2;
    const int tig  = lane & 3;
    const float scale = 0.08838834764831845f;

    const int mA = warp * 16 + g;
    const int mB = mA + 8;
    const int tA = t0 + (mA & 31), tB = t0 + (mB & 31);
    const int hA = gh * 4 + (mA >> 5), hB = gh * 4 + (mB >> 5);

    uint32_t qa[16][4];
    const float* qAp = q + ((size_t)tA * 16 + hA) * 128;
    const float* qBp = q + ((size_t)tB * 16 + hB) * 128;
#pragma unroll
    for (int ks = 0; ks < 16; ks++) {
        qa[ks][0] = f2tf(qAp[8 * ks + tig]);
        qa[ks][1] = f2tf(qBp[8 * ks + tig]);
        qa[ks][2] = f2tf(qAp[8 * ks + tig + 4]);
        qa[ks][3] = f2tf(qBp[8 * ks + tig + 4]);
    }

    float oa[16][4];
#pragma unroll
    for (int i = 0; i < 16; i++)
#pragma unroll
        for (int r = 0; r < 4; r++) oa[i][r] = 0.0f;
    float rmA = -1e30f, rmB = -1e30f, rlA = 0.0f, rlB = 0.0f;

    uint32_t* Pw = &KP[warp * 16 * PSTR];

    for (int c = 0; c < 17; c++) {
        const int sb = t0 - 512 + 32 * c;
        if (sb + 31 < 0) continue;

#pragma unroll
        for (int i = 0; i < 4; i++) {
            int idx = tid + 256 * i;
            int row = idx >> 5;
            int c4  = (idx & 31) * 4;
            int s = sb + row;
            float4 k4 = make_float4(0.f, 0.f, 0.f, 0.f);
            float4 v4 = make_float4(0.f, 0.f, 0.f, 0.f);
            if (s >= 0) {
                k4 = *(const float4*)&k[((size_t)s * 4 + gh) * 128 + c4];
                v4 = *(const float4*)&v[((size_t)s * 4 + gh) * 128 + c4];
            }
            uint4 kp = make_uint4(f2tf(k4.x), f2tf(k4.y), f2tf(k4.z), f2tf(k4.w));
            uint4 vp = make_uint4(f2tf(v4.x), f2tf(v4.y), f2tf(v4.z), f2tf(v4.w));
            *(uint4*)&KP[row * KSTR + c4] = kp;
            *(uint4*)&Vs[row * KSTR + c4] = vp;
        }
        __syncthreads();

        float sf[4][4];
#pragma unroll
        for (int ni = 0; ni < 4; ni++)
#pragma unroll
            for (int r = 0; r < 4; r++) sf[ni][r] = 0.0f;
#pragma unroll
        for (int ks = 0; ks < 16; ks++) {
            const int kk = ks * 8;
#pragma unroll
            for (int ni = 0; ni < 4; ni++) {
                uint32_t b0 = KP[(ni * 8 + g) * KSTR + kk + tig];
                uint32_t b1 = KP[(ni * 8 + g) * KSTR + kk + tig + 4];
                mma_tf32(sf[ni], qa[ks], b0, b1);
            }
        }
        __syncthreads();

        float cmA = -1e30f, cmB = -1e30f;
#pragma unroll
        for (int ni = 0; ni < 4; ni++) {
#pragma unroll
            for (int jj = 0; jj < 2; jj++) {
                const int s = sb + ni * 8 + tig * 2 + jj;
                bool okA = (s >= 0) && (s <= tA) && (tA - s <= 512);
                bool okB = (s >= 0) && (s <= tB) && (tB - s <= 512);
                sf[ni][jj]     = okA ? sf[ni][jj]     * scale : -1e30f;
                sf[ni][2 + jj] = okB ? sf[ni][2 + jj] * scale : -1e30f;
                cmA = fmaxf(cmA, sf[ni][jj]);
                cmB = fmaxf(cmB, sf[ni][2 + jj]);
            }
        }
        cmA = fmaxf(cmA, __shfl_xor_sync(0xffffffffu, cmA, 1));
        cmA = fmaxf(cmA, __shfl_xor_sync(0xffffffffu, cmA, 2));
        cmB = fmaxf(cmB, __shfl_xor_sync(0xffffffffu, cmB, 1));
        cmB = fmaxf(cmB, __shfl_xor_sync(0xffffffffu, cmB, 2));

        const float nmA = fmaxf(rmA, cmA), nmB = fmaxf(rmB, cmB);
        const float alA = __expf(rmA - nmA), alB = __expf(rmB - nmB);
        rmA = nmA; rmB = nmB;

        float clA = 0.f, clB = 0.f;
#pragma unroll
        for (int ni = 0; ni < 4; ni++) {
            float p0 = __expf(sf[ni][0] - nmA);
            float p1 = __expf(sf[ni][1] - nmA);
            float p2 = __expf(sf[ni][2] - nmB);
            float p3 = __expf(sf[ni][3] - nmB);
            clA += p0 + p1; clB += p2 + p3;
            const int col = ni * 8 + tig * 2;
            Pw[g * PSTR + col]           = f2tf(p0);
            Pw[g * PSTR + col + 1]       = f2tf(p1);
            Pw[(g + 8) * PSTR + col]     = f2tf(p2);
            Pw[(g + 8) * PSTR + col + 1] = f2tf(p3);
        }
        clA += __shfl_xor_sync(0xffffffffu, clA, 1);
        clA += __shfl_xor_sync(0xffffffffu, clA, 2);
        clB += __shfl_xor_sync(0xffffffffu, clB, 1);
        clB += __shfl_xor_sync(0xffffffffu, clB, 2);
        rlA = rlA * alA + clA;
        rlB = rlB * alB + clB;

#pragma unroll
        for (int ni2 = 0; ni2 < 16; ni2++) {
            oa[ni2][0] *= alA; oa[ni2][1] *= alA;
            oa[ni2][2] *= alB; oa[ni2][3] *= alB;
        }
        __syncwarp();

#pragma unroll
        for (int ks = 0; ks < 4; ks++) {
            const int kk = ks * 8;
            uint32_t pa[4];
            pa[0] = Pw[g * PSTR + kk + tig];
            pa[1] = Pw[(g + 8) * PSTR + kk + tig];
            pa[2] = Pw[g * PSTR + kk + tig + 4];
            pa[3] = Pw[(g + 8) * PSTR + kk + tig + 4];
#pragma unroll
            for (int ni2 = 0; ni2 < 16; ni2++) {
                uint32_t b0 = Vs[(kk + tig) * KSTR + ni2 * 8 + g];
                uint32_t b1 = Vs[(kk + tig + 4) * KSTR + ni2 * 8 + g];
                mma_tf32(oa[ni2], pa, b0, b1);
            }
        }
        __syncthreads();
    }

    const float ilA = 1.0f / rlA, ilB = 1.0f / rlB;
    float* oAp = out + ((size_t)tA * 16 + hA) * 128;
    float* oBp = out + ((size_t)tB * 16 + hB) * 128;
#pragma unroll
    for (int ni2 = 0; ni2 < 16; ni2++) {
        const int d0 = ni2 * 8 + tig * 2;
        *(float2*)&oAp[d0] = make_float2(oa[ni2][0] * ilA, oa[ni2][1] * ilA);
        *(float2*)&oBp[d0] = make_float2(oa[ni2][2] * ilB, oa[ni2][3] * ilB);
    }
}

// ---------------- launcher -------------------------------------------------
extern "C" void kernel_launch(void* const* d_in, const int* in_sizes, int n_in,
                              void* d_out, int out_size)
{
    const float* x  = (const float*)d_in[0];
    const float* wq = (const float*)d_in[1];
    const float* wk = (const float*)d_in[2];
    const float* wv = (const float*)d_in[3];
    const float* wo = (const float*)d_in[4];
    float* out = (float*)d_out;

    float *q, *k, *v, *att;
    uint32_t *xt, *wt, *ot, *at;
    cudaGetSymbolAddress((void**)&q,   g_q);
    cudaGetSymbolAddress((void**)&k,   g_k);
    cudaGetSymbolAddress((void**)&v,   g_v);
    cudaGetSymbolAddress((void**)&att, g_att);
    cudaGetSymbolAddress((void**)&xt,  g_xt);
    cudaGetSymbolAddress((void**)&wt,  g_wt);
    cudaGetSymbolAddress((void**)&ot,  g_ot);
    cudaGetSymbolAddress((void**)&at,  g_at);

    cudaFuncSetAttribute(gemm_w64, cudaFuncAttributeMaxDynamicSharedMemorySize,
                         GEMM_SMEM);

    // pre-convert all GEMM operands to tf32 (weights written concatenated)
    conv_tf32<<<8192, 256>>>(x,  xt, TLEN * 2048);
    conv_tf32<<<4096, 256>>>(wq, wt,              2048 * 2048);
    conv_tf32<<<1024, 256>>>(wk, wt + 2048 * 2048, 512 * 2048);
    conv_tf32<<<1024, 256>>>(wv, wt + 2560 * 2048, 512 * 2048);
    conv_tf32<<<4096, 256>>>(wo, ot, 2048 * 2048);

    // fused QKV projection
    gemm_w64<<<dim3(24, 32), 128, GEMM_SMEM>>>(xt, wt,
                                               q, 2048, 2048,
                                               k, 512, 512,
                                               v, 512, 2048);

    rope_kernel<<<dim3(TLEN, 5), 256>>>(q, k);

    attn_mma<<<dim3(TLEN / 32, 4), 256>>>(q, k, v, att);

    // output projection
    conv_tf32<<<8192, 256>>>(att, at, TLEN * 2048);
    gemm_w64<<<dim3(16, 32), 128, GEMM_SMEM>>>(at, ot,
                                               out, 2048, 2048,
                                               out, 0, 2048,
                                               out, 2048, 2048);
}